// round 1
// baseline (speedup 1.0000x reference)
#include <cuda_runtime.h>
#include <cuda_bf16.h>
#include <math.h>

// Problem constants
#define BB 4
#define TT 256
#define UU 128
#define EE 512
#define DD 640
#define HH 512
#define VV 640

// Scratch for projected features (no cudaMalloc allowed)
__device__ float g_enc_proj[BB * TT * HH];   // [1024, 512]
__device__ float g_dec_proj[BB * UU * HH];   // [512, 512]

// ---------------------------------------------------------------------------
// Generic small GEMM with optional bias: C[M,N] = A[M,K] @ W[K,N] (+ bias[N])
// Tile 64x64, 256 threads (16x16), 4x4 micro-tile, K-chunk 32.
// All dims divisible by tile sizes for our shapes.
// ---------------------------------------------------------------------------
__global__ __launch_bounds__(256) void proj_kernel(
    const float* __restrict__ A, const float* __restrict__ W,
    const float* __restrict__ bias, float* __restrict__ C,
    int M, int N, int K)
{
    __shared__ float Ast[32][65];  // transposed: [k][m]
    __shared__ float Ws[32][68];   // [k][n]

    int tid = threadIdx.x;
    int tx = tid & 15;
    int ty = tid >> 4;
    int m0 = blockIdx.y * 64;
    int n0 = blockIdx.x * 64;

    float acc[4][4];
#pragma unroll
    for (int i = 0; i < 4; i++)
#pragma unroll
        for (int j = 0; j < 4; j++) acc[i][j] = 0.0f;

    for (int k0 = 0; k0 < K; k0 += 32) {
        // Load A tile 64x32 -> Ast (transposed)
#pragma unroll
        for (int l = 0; l < 8; l++) {
            int idx = tid + l * 256;
            int r = idx >> 5;
            int c = idx & 31;
            Ast[c][r] = A[(m0 + r) * K + k0 + c];
        }
        // Load W tile 32x64 -> Ws
#pragma unroll
        for (int l = 0; l < 8; l++) {
            int idx = tid + l * 256;
            int r = idx >> 6;
            int c = idx & 63;
            Ws[r][c] = W[(k0 + r) * N + n0 + c];
        }
        __syncthreads();

#pragma unroll
        for (int k = 0; k < 32; k++) {
            float a[4], b[4];
#pragma unroll
            for (int i = 0; i < 4; i++) a[i] = Ast[k][ty * 4 + i];
#pragma unroll
            for (int j = 0; j < 4; j++) b[j] = Ws[k][tx * 4 + j];
#pragma unroll
            for (int i = 0; i < 4; i++)
#pragma unroll
                for (int j = 0; j < 4; j++)
                    acc[i][j] = fmaf(a[i], b[j], acc[i][j]);
        }
        __syncthreads();
    }

#pragma unroll
    for (int i = 0; i < 4; i++) {
        int row = m0 + ty * 4 + i;
#pragma unroll
        for (int j = 0; j < 4; j++) {
            int col = n0 + tx * 4 + j;
            float v = acc[i][j];
            if (bias) v += bias[col];
            C[row * N + col] = v;
        }
    }
}

// ---------------------------------------------------------------------------
// Joint kernel: for each (b,t) tile, A[u][h] = tanh(enc_proj[b,t,h] +
// dec_proj[b,u,h]); out[b,t,u,v] = A @ W_out + b_out.
// CTA tile: M=128 (all u), N=128 (v-slice), K=512 chunked by 32.
// 256 threads (16x16), 8x8 micro-tile.
// ---------------------------------------------------------------------------
__global__ __launch_bounds__(256, 2) void joint_kernel(
    const float* __restrict__ W_out,   // [H, V] row-major
    const float* __restrict__ b_out,   // [V]
    float* __restrict__ out)           // [B*T*U, V]
{
    __shared__ float As[128][33];   // tanh(enc+dec): [u][k]
    __shared__ float Bs[32][132];   // W_out chunk:   [k][v]

    int tid = threadIdx.x;
    int tx = tid & 15;
    int ty = tid >> 4;

    int bt = blockIdx.y;            // 0..1023  (b*T + t)
    int b  = bt >> 8;               // T = 256
    int v0 = blockIdx.x * 128;

    const float* encp = g_enc_proj + bt * HH;        // [H]
    const float* decp = g_dec_proj + b * UU * HH;    // [U, H]

    float acc[8][8];
#pragma unroll
    for (int i = 0; i < 8; i++)
#pragma unroll
        for (int j = 0; j < 8; j++) acc[i][j] = 0.0f;

    const int k_local = tid & 31;     // constant per thread across l
    const int u_base  = tid >> 5;     // 0..7
    const int c_v     = tid & 127;    // constant per thread across l
    const int k_base  = tid >> 7;     // 0..1

    for (int h0 = 0; h0 < HH; h0 += 32) {
        // --- build A chunk: 128 x 32, fused tanh(enc + dec) ---
        float e = encp[h0 + k_local];
#pragma unroll
        for (int l = 0; l < 16; l++) {
            int u = u_base + l * 8;
            float dv = decp[u * HH + h0 + k_local];
            As[u][k_local] = tanhf(e + dv);
        }
        // --- load W_out chunk: 32 x 128 ---
#pragma unroll
        for (int l = 0; l < 16; l++) {
            int kk = k_base + l * 2;
            Bs[kk][c_v] = W_out[(h0 + kk) * VV + v0 + c_v];
        }
        __syncthreads();

#pragma unroll
        for (int k = 0; k < 32; k++) {
            float a[8];
#pragma unroll
            for (int i = 0; i < 8; i++) a[i] = As[ty * 8 + i][k];
            float4 bv0 = *reinterpret_cast<const float4*>(&Bs[k][tx * 8]);
            float4 bv1 = *reinterpret_cast<const float4*>(&Bs[k][tx * 8 + 4]);
            float bfr[8] = {bv0.x, bv0.y, bv0.z, bv0.w, bv1.x, bv1.y, bv1.z, bv1.w};
#pragma unroll
            for (int i = 0; i < 8; i++)
#pragma unroll
                for (int j = 0; j < 8; j++)
                    acc[i][j] = fmaf(a[i], bfr[j], acc[i][j]);
        }
        __syncthreads();
    }

    // --- epilogue: add bias, store [128 x 128] tile ---
    float bj[8];
#pragma unroll
    for (int j = 0; j < 8; j++) bj[j] = b_out[v0 + tx * 8 + j];

#pragma unroll
    for (int i = 0; i < 8; i++) {
        long long row = (long long)bt * UU + (ty * 8 + i);
        float* po = out + row * VV + v0 + tx * 8;
        float4 s0 = make_float4(acc[i][0] + bj[0], acc[i][1] + bj[1],
                                acc[i][2] + bj[2], acc[i][3] + bj[3]);
        float4 s1 = make_float4(acc[i][4] + bj[4], acc[i][5] + bj[5],
                                acc[i][6] + bj[6], acc[i][7] + bj[7]);
        *reinterpret_cast<float4*>(po)     = s0;
        *reinterpret_cast<float4*>(po + 4) = s1;
    }
}

extern "C" void kernel_launch(void* const* d_in, const int* in_sizes, int n_in,
                              void* d_out, int out_size)
{
    const float* enc_out = (const float*)d_in[0];  // [B,T,E]
    const float* dec_out = (const float*)d_in[1];  // [B,U,D]
    const float* W_enc   = (const float*)d_in[2];  // [E,H]
    const float* b_enc   = (const float*)d_in[3];  // [H]
    const float* W_dec   = (const float*)d_in[4];  // [D,H]
    const float* W_out   = (const float*)d_in[5];  // [H,V]
    const float* b_out   = (const float*)d_in[6];  // [V]
    float* out = (float*)d_out;

    // enc projection: [B*T, E] @ [E, H] + b_enc -> g_enc_proj
    {
        float* enc_proj_ptr = nullptr;
        cudaGetSymbolAddress((void**)&enc_proj_ptr, g_enc_proj);
        dim3 grid(HH / 64, (BB * TT) / 64);  // (8, 16)
        proj_kernel<<<grid, 256>>>(enc_out, W_enc, b_enc, enc_proj_ptr,
                                   BB * TT, HH, EE);
    }
    // dec projection: [B*U, D] @ [D, H] -> g_dec_proj
    {
        float* dec_proj_ptr = nullptr;
        cudaGetSymbolAddress((void**)&dec_proj_ptr, g_dec_proj);
        dim3 grid(HH / 64, (BB * UU) / 64);  // (8, 8)
        proj_kernel<<<grid, 256>>>(dec_out, W_dec, nullptr, dec_proj_ptr,
                                   BB * UU, HH, DD);
    }
    // joint: 1024 (b,t) tiles x 5 v-tiles
    {
        dim3 grid(VV / 128, BB * TT);  // (5, 1024)
        joint_kernel<<<grid, 256>>>(W_out, b_out, out);
    }
}

// round 4
// speedup vs baseline: 3.8295x; 3.8295x over previous
#include <cuda_runtime.h>
#include <cuda_fp16.h>
#include <math.h>
#include <stdint.h>

// ---------------- problem constants ----------------
#define BB 4
#define TT 256
#define UU 128
#define EE 512
#define DD 640
#define HH 512
#define VV 640
#define BT (BB*TT)          // 1024

// ---------------- device scratch (no cudaMalloc allowed) ----------------
__device__ float g_enc_proj[BT * HH];        // [1024, 512]
__device__ float g_dec_proj[BB * UU * HH];   // [512, 512]
__device__ __half g_A_hi[BT * UU * HH];      // fp16 hi of tanh  (134 MB)
__device__ __half g_A_lo[BT * UU * HH];      // fp16 lo residual (134 MB)
__device__ __half g_W_h[VV * HH];            // W_out transposed [v][h], fp16

// ---------------- PTX helpers (baseline ISA only — no sm_103a features) ---
__device__ __forceinline__ uint32_t smem_u32(const void* p) {
    uint32_t a;
    asm("{ .reg .u64 t; cvta.to.shared.u64 t, %1; cvt.u32.u64 %0, t; }"
        : "=r"(a) : "l"(p));
    return a;
}
__device__ __forceinline__ void cp_async16(uint32_t dst, const void* src) {
    asm volatile("cp.async.cg.shared.global [%0], [%1], 16;"
                 :: "r"(dst), "l"(src) : "memory");
}
__device__ __forceinline__ void cp_commit() {
    asm volatile("cp.async.commit_group;" ::: "memory");
}
__device__ __forceinline__ void cp_wait1() {
    asm volatile("cp.async.wait_group 1;" ::: "memory");
}
__device__ __forceinline__ void cp_wait0() {
    asm volatile("cp.async.wait_group 0;" ::: "memory");
}
__device__ __forceinline__ void ldsm_x4(uint32_t& r0, uint32_t& r1,
                                        uint32_t& r2, uint32_t& r3, uint32_t addr) {
    asm volatile("ldmatrix.sync.aligned.m8n8.x4.shared.b16 {%0,%1,%2,%3}, [%4];"
                 : "=r"(r0), "=r"(r1), "=r"(r2), "=r"(r3) : "r"(addr));
}
__device__ __forceinline__ void ldsm_x2(uint32_t& r0, uint32_t& r1, uint32_t addr) {
    asm volatile("ldmatrix.sync.aligned.m8n8.x2.shared.b16 {%0,%1}, [%2];"
                 : "=r"(r0), "=r"(r1) : "r"(addr));
}
__device__ __forceinline__ void mma16816(float* c, uint32_t a0, uint32_t a1,
                                         uint32_t a2, uint32_t a3,
                                         uint32_t b0, uint32_t b1) {
    asm volatile(
        "mma.sync.aligned.m16n8k16.row.col.f32.f16.f16.f32 "
        "{%0,%1,%2,%3}, {%4,%5,%6,%7}, {%8,%9}, {%0,%1,%2,%3};"
        : "+f"(c[0]), "+f"(c[1]), "+f"(c[2]), "+f"(c[3])
        : "r"(a0), "r"(a1), "r"(a2), "r"(a3), "r"(b0), "r"(b1));
}

// ---------------------------------------------------------------------------
// proj: C[M,N] = A[M,K] @ W[K,N] (+ bias). fp32, 64x64 tile.
// ---------------------------------------------------------------------------
__global__ __launch_bounds__(256) void proj_kernel(
    const float* __restrict__ A, const float* __restrict__ W,
    const float* __restrict__ bias, float* __restrict__ C,
    int M, int N, int K)
{
    __shared__ float Ast[32][65];
    __shared__ float Ws[32][68];
    int tid = threadIdx.x;
    int tx = tid & 15, ty = tid >> 4;
    int m0 = blockIdx.y * 64, n0 = blockIdx.x * 64;

    float acc[4][4];
#pragma unroll
    for (int i = 0; i < 4; i++)
#pragma unroll
        for (int j = 0; j < 4; j++) acc[i][j] = 0.0f;

    for (int k0 = 0; k0 < K; k0 += 32) {
#pragma unroll
        for (int l = 0; l < 8; l++) {
            int idx = tid + l * 256;
            Ast[idx & 31][idx >> 5] = A[(m0 + (idx >> 5)) * K + k0 + (idx & 31)];
        }
#pragma unroll
        for (int l = 0; l < 8; l++) {
            int idx = tid + l * 256;
            Ws[idx >> 6][idx & 63] = W[(k0 + (idx >> 6)) * N + n0 + (idx & 63)];
        }
        __syncthreads();
#pragma unroll
        for (int k = 0; k < 32; k++) {
            float a[4], b[4];
#pragma unroll
            for (int i = 0; i < 4; i++) a[i] = Ast[k][ty * 4 + i];
#pragma unroll
            for (int j = 0; j < 4; j++) b[j] = Ws[k][tx * 4 + j];
#pragma unroll
            for (int i = 0; i < 4; i++)
#pragma unroll
                for (int j = 0; j < 4; j++)
                    acc[i][j] = fmaf(a[i], b[j], acc[i][j]);
        }
        __syncthreads();
    }
#pragma unroll
    for (int i = 0; i < 4; i++)
#pragma unroll
        for (int j = 0; j < 4; j++) {
            float v = acc[i][j];
            if (bias) v += bias[n0 + tx * 4 + j];
            C[(m0 + ty * 4 + i) * N + n0 + tx * 4 + j] = v;
        }
}

// ---------------------------------------------------------------------------
// prep_w: transpose + fp16 cast of W_out [H,V] -> [V,H]
// ---------------------------------------------------------------------------
__global__ __launch_bounds__(256) void prep_w_kernel(const float* __restrict__ W_out)
{
    int idx = blockIdx.x * 256 + threadIdx.x;
    if (idx >= VV * HH) return;
    int v = idx / HH, h = idx - v * HH;
    g_W_h[idx] = __float2half(W_out[h * VV + v]);
}

// ---------------------------------------------------------------------------
// act: A[bt][u][h] = tanh(enc_proj[bt][h] + dec_proj[b][u][h]) -> fp16 hi/lo
// ---------------------------------------------------------------------------
__global__ __launch_bounds__(256) void act_kernel()
{
    int bt = blockIdx.x;
    int b = bt >> 8;
    int u = blockIdx.y * 4 + (threadIdx.x >> 6);
    int h = (threadIdx.x & 63) * 8;
    const float* ep = g_enc_proj + bt * HH + h;
    const float* dp = g_dec_proj + (b * UU + u) * HH + h;
    float4 e0 = *(const float4*)ep, e1 = *(const float4*)(ep + 4);
    float4 d0 = *(const float4*)dp, d1 = *(const float4*)(dp + 4);
    float x[8] = {e0.x + d0.x, e0.y + d0.y, e0.z + d0.z, e0.w + d0.w,
                  e1.x + d1.x, e1.y + d1.y, e1.z + d1.z, e1.w + d1.w};
    __align__(16) __half hi8[8];
    __align__(16) __half lo8[8];
#pragma unroll
    for (int i = 0; i < 8; i++) {
        float t = tanhf(x[i]);
        __half hi = __float2half(t);
        hi8[i] = hi;
        lo8[i] = __float2half(t - __half2float(hi));
    }
    size_t o = ((size_t)bt * UU + u) * HH + h;
    *(uint4*)(g_A_hi + o) = *(const uint4*)hi8;
    *(uint4*)(g_A_lo + o) = *(const uint4*)lo8;
}

// ---------------------------------------------------------------------------
// joint GEMM (HMMA): per (bt, v-tile): out[128u,128v] = A[128,512]@W^T + bias
// 2-term fp16 split: D = Ah*Wh + Al*Wh. 8 warps, 64x32 per warp.
// K chunks of 64, cp.async double-buffered, XOR-swizzled smem rows (128B).
// ---------------------------------------------------------------------------
#define KC 64
#define STAGE 49152      // Ah 16K + Al 16K + Wh 16K
#define OFF_AL 16384
#define OFF_W  32768

__global__ __launch_bounds__(256) void joint_hmma_kernel(
    const float* __restrict__ b_out, float* __restrict__ out)
{
    extern __shared__ char smem[];
    uint32_t sb = smem_u32(smem);
    int tid = threadIdx.x;
    int lane = tid & 31;
    int wid = tid >> 5;
    int bt = blockIdx.y;
    int v0 = blockIdx.x * 128;

    int wm = (wid & 1) * 64;     // warp m offset (u)
    int wn = (wid >> 1) * 32;    // warp n offset (v)

    const __half* Ahg = g_A_hi + (size_t)bt * UU * HH;
    const __half* Alg = g_A_lo + (size_t)bt * UU * HH;
    const __half* Wg  = g_W_h + (size_t)v0 * HH;

    float acc[4][4][4];
#pragma unroll
    for (int i = 0; i < 4; i++)
#pragma unroll
        for (int j = 0; j < 4; j++)
#pragma unroll
            for (int k = 0; k < 4; k++) acc[i][j][k] = 0.0f;

    // ---- fill lambda: copy chunk k0 into buffer bsel ----
    auto fill = [&](int bsel, int k0) {
        uint32_t base = sb + bsel * STAGE;
#pragma unroll
        for (int l = 0; l < 4; l++) {
            int idx = tid + l * 256;      // 0..1023
            int r = idx >> 3;             // row 0..127
            int c = idx & 7;              // 16B chunk 0..7
            uint32_t doff = (uint32_t)(r * 128 + ((c ^ (r & 7)) << 4));
            const __half* sa = Ahg + (size_t)r * HH + k0 + c * 8;
            const __half* sl = Alg + (size_t)r * HH + k0 + c * 8;
            const __half* sw = Wg  + (size_t)r * HH + k0 + c * 8;
            cp_async16(base + doff, sa);
            cp_async16(base + OFF_AL + doff, sl);
            cp_async16(base + OFF_W  + doff, sw);
        }
    };

    fill(0, 0);
    cp_commit();

#pragma unroll 1
    for (int c = 0; c < HH / KC; c++) {
        if (c < HH / KC - 1) {
            fill((c + 1) & 1, (c + 1) * KC);
            cp_commit();
            cp_wait1();
        } else {
            cp_wait0();
        }
        __syncthreads();

        uint32_t sA  = sb + (c & 1) * STAGE;
        uint32_t sAl = sA + OFF_AL;
        uint32_t sW  = sA + OFF_W;

#pragma unroll
        for (int s = 0; s < 4; s++) {
            // B fragments for 4 n-tiles (shared by hi and lo terms)
            uint32_t b0[4], b1[4];
#pragma unroll
            for (int ni = 0; ni < 4; ni++) {
                int row = wn + ni * 8 + (lane & 7);
                int chunk = 2 * s + ((lane >> 3) & 1);
                uint32_t addr = sW + row * 128 + (((chunk) ^ (row & 7)) << 4);
                ldsm_x2(b0[ni], b1[ni], addr);
            }
#pragma unroll
            for (int mi = 0; mi < 4; mi++) {
                int row = wm + mi * 16 + ((lane >> 3) & 1) * 8 + (lane & 7);
                int chunk = 2 * s + (lane >> 4);
                uint32_t off = (uint32_t)(row * 128 + ((chunk ^ (row & 7)) << 4));
                uint32_t a0, a1, a2, a3;
                ldsm_x4(a0, a1, a2, a3, sA + off);
#pragma unroll
                for (int ni = 0; ni < 4; ni++)
                    mma16816(acc[mi][ni], a0, a1, a2, a3, b0[ni], b1[ni]);
                ldsm_x4(a0, a1, a2, a3, sAl + off);
#pragma unroll
                for (int ni = 0; ni < 4; ni++)
                    mma16816(acc[mi][ni], a0, a1, a2, a3, b0[ni], b1[ni]);
            }
        }
        __syncthreads();
    }

    // ---- epilogue: bias + float2 stores straight from registers ----
    int gid = lane >> 2;
    int tig = lane & 3;
    float2 bias2[4];
#pragma unroll
    for (int ni = 0; ni < 4; ni++)
        bias2[ni] = *(const float2*)(b_out + v0 + wn + ni * 8 + tig * 2);

    float* obase = out + (size_t)bt * UU * VV + v0;
#pragma unroll
    for (int mi = 0; mi < 4; mi++) {
        int u0 = wm + mi * 16 + gid;
#pragma unroll
        for (int ni = 0; ni < 4; ni++) {
            int v = wn + ni * 8 + tig * 2;
            float2 r0 = make_float2(acc[mi][ni][0] + bias2[ni].x,
                                    acc[mi][ni][1] + bias2[ni].y);
            float2 r1 = make_float2(acc[mi][ni][2] + bias2[ni].x,
                                    acc[mi][ni][3] + bias2[ni].y);
            *(float2*)(obase + (size_t)u0 * VV + v) = r0;
            *(float2*)(obase + (size_t)(u0 + 8) * VV + v) = r1;
        }
    }
}

// ---------------------------------------------------------------------------
extern "C" void kernel_launch(void* const* d_in, const int* in_sizes, int n_in,
                              void* d_out, int out_size)
{
    const float* enc_out = (const float*)d_in[0];
    const float* dec_out = (const float*)d_in[1];
    const float* W_enc   = (const float*)d_in[2];
    const float* b_enc   = (const float*)d_in[3];
    const float* W_dec   = (const float*)d_in[4];
    const float* W_out   = (const float*)d_in[5];
    const float* b_out   = (const float*)d_in[6];
    float* out = (float*)d_out;

    cudaFuncSetAttribute(joint_hmma_kernel,
                         cudaFuncAttributeMaxDynamicSharedMemorySize, 2 * STAGE);

    float* enc_proj_ptr = nullptr;
    float* dec_proj_ptr = nullptr;
    cudaGetSymbolAddress((void**)&enc_proj_ptr, g_enc_proj);
    cudaGetSymbolAddress((void**)&dec_proj_ptr, g_dec_proj);

    {
        dim3 grid(HH / 64, (BB * TT) / 64);
        proj_kernel<<<grid, 256>>>(enc_out, W_enc, b_enc, enc_proj_ptr, BB * TT, HH, EE);
    }
    {
        dim3 grid(HH / 64, (BB * UU) / 64);
        proj_kernel<<<grid, 256>>>(dec_out, W_dec, nullptr, dec_proj_ptr, BB * UU, HH, DD);
    }
    prep_w_kernel<<<(VV * HH + 255) / 256, 256>>>(W_out);
    {
        dim3 grid(BT, UU / 4);
        act_kernel<<<grid, 256>>>();
    }
    {
        dim3 grid(VV / 128, BT);   // (5, 1024)
        joint_hmma_kernel<<<grid, 256, 2 * STAGE>>>(b_out, out);
    }
}

// round 5
// speedup vs baseline: 5.7390x; 1.4986x over previous
#include <cuda_runtime.h>
#include <cuda_fp16.h>
#include <math.h>
#include <stdint.h>

// ---------------- problem constants ----------------
#define BB 4
#define TT 256
#define UU 128
#define EE 512
#define DD 640
#define HH 512
#define VV 640
#define BT (BB*TT)          // 1024

// ---------------- device scratch (no cudaMalloc allowed) ----------------
__device__ float g_enc_proj[BT * HH];        // [1024, 512]
__device__ float g_dec_proj[BB * UU * HH];   // [512, 512]
__device__ __half g_A_h[BT * UU * HH];       // fp16 tanh activations (134 MB)
__device__ __half g_W_h[VV * HH];            // W_out transposed [v][h], fp16

// ---------------- PTX helpers (baseline ISA only) ----------------
__device__ __forceinline__ uint32_t smem_u32(const void* p) {
    uint32_t a;
    asm("{ .reg .u64 t; cvta.to.shared.u64 t, %1; cvt.u32.u64 %0, t; }"
        : "=r"(a) : "l"(p));
    return a;
}
__device__ __forceinline__ void cp_async16(uint32_t dst, const void* src) {
    asm volatile("cp.async.cg.shared.global [%0], [%1], 16;"
                 :: "r"(dst), "l"(src) : "memory");
}
__device__ __forceinline__ void cp_commit() {
    asm volatile("cp.async.commit_group;" ::: "memory");
}
__device__ __forceinline__ void cp_wait1() {
    asm volatile("cp.async.wait_group 1;" ::: "memory");
}
__device__ __forceinline__ void cp_wait0() {
    asm volatile("cp.async.wait_group 0;" ::: "memory");
}
__device__ __forceinline__ void ldsm_x4(uint32_t& r0, uint32_t& r1,
                                        uint32_t& r2, uint32_t& r3, uint32_t addr) {
    asm volatile("ldmatrix.sync.aligned.m8n8.x4.shared.b16 {%0,%1,%2,%3}, [%4];"
                 : "=r"(r0), "=r"(r1), "=r"(r2), "=r"(r3) : "r"(addr));
}
__device__ __forceinline__ void ldsm_x2(uint32_t& r0, uint32_t& r1, uint32_t addr) {
    asm volatile("ldmatrix.sync.aligned.m8n8.x2.shared.b16 {%0,%1}, [%2];"
                 : "=r"(r0), "=r"(r1) : "r"(addr));
}
__device__ __forceinline__ void mma16816(float* c, uint32_t a0, uint32_t a1,
                                         uint32_t a2, uint32_t a3,
                                         uint32_t b0, uint32_t b1) {
    asm volatile(
        "mma.sync.aligned.m16n8k16.row.col.f32.f16.f16.f32 "
        "{%0,%1,%2,%3}, {%4,%5,%6,%7}, {%8,%9}, {%0,%1,%2,%3};"
        : "+f"(c[0]), "+f"(c[1]), "+f"(c[2]), "+f"(c[3])
        : "r"(a0), "r"(a1), "r"(a2), "r"(a3), "r"(b0), "r"(b1));
}

// ---------------------------------------------------------------------------
// proj: C[M,N] = A[M,K] @ W[K,N] (+ bias). fp32, 64x64 tile.
// ---------------------------------------------------------------------------
__global__ __launch_bounds__(256) void proj_kernel(
    const float* __restrict__ A, const float* __restrict__ W,
    const float* __restrict__ bias, float* __restrict__ C,
    int M, int N, int K)
{
    __shared__ float Ast[32][65];
    __shared__ float Ws[32][68];
    int tid = threadIdx.x;
    int tx = tid & 15, ty = tid >> 4;
    int m0 = blockIdx.y * 64, n0 = blockIdx.x * 64;

    float acc[4][4];
#pragma unroll
    for (int i = 0; i < 4; i++)
#pragma unroll
        for (int j = 0; j < 4; j++) acc[i][j] = 0.0f;

    for (int k0 = 0; k0 < K; k0 += 32) {
#pragma unroll
        for (int l = 0; l < 8; l++) {
            int idx = tid + l * 256;
            Ast[idx & 31][idx >> 5] = A[(m0 + (idx >> 5)) * K + k0 + (idx & 31)];
        }
#pragma unroll
        for (int l = 0; l < 8; l++) {
            int idx = tid + l * 256;
            Ws[idx >> 6][idx & 63] = W[(k0 + (idx >> 6)) * N + n0 + (idx & 63)];
        }
        __syncthreads();
#pragma unroll
        for (int k = 0; k < 32; k++) {
            float a[4], b[4];
#pragma unroll
            for (int i = 0; i < 4; i++) a[i] = Ast[k][ty * 4 + i];
#pragma unroll
            for (int j = 0; j < 4; j++) b[j] = Ws[k][tx * 4 + j];
#pragma unroll
            for (int i = 0; i < 4; i++)
#pragma unroll
                for (int j = 0; j < 4; j++)
                    acc[i][j] = fmaf(a[i], b[j], acc[i][j]);
        }
        __syncthreads();
    }
#pragma unroll
    for (int i = 0; i < 4; i++)
#pragma unroll
        for (int j = 0; j < 4; j++) {
            float v = acc[i][j];
            if (bias) v += bias[n0 + tx * 4 + j];
            C[(m0 + ty * 4 + i) * N + n0 + tx * 4 + j] = v;
        }
}

// ---------------------------------------------------------------------------
// prep_w: transpose + fp16 cast of W_out [H,V] -> [V,H]
// ---------------------------------------------------------------------------
__global__ __launch_bounds__(256) void prep_w_kernel(const float* __restrict__ W_out)
{
    int idx = blockIdx.x * 256 + threadIdx.x;
    if (idx >= VV * HH) return;
    int v = idx / HH, h = idx - v * HH;
    g_W_h[idx] = __float2half(W_out[h * VV + v]);
}

// ---------------------------------------------------------------------------
// act: A[bt][u][h] = tanh(enc_proj[bt][h] + dec_proj[b][u][h]) -> fp16
// ---------------------------------------------------------------------------
__global__ __launch_bounds__(256) void act_kernel()
{
    int bt = blockIdx.x;
    int b = bt >> 8;
    int u = blockIdx.y * 4 + (threadIdx.x >> 6);
    int h = (threadIdx.x & 63) * 8;
    const float* ep = g_enc_proj + bt * HH + h;
    const float* dp = g_dec_proj + (b * UU + u) * HH + h;
    float4 e0 = *(const float4*)ep, e1 = *(const float4*)(ep + 4);
    float4 d0 = *(const float4*)dp, d1 = *(const float4*)(dp + 4);
    float x[8] = {e0.x + d0.x, e0.y + d0.y, e0.z + d0.z, e0.w + d0.w,
                  e1.x + d1.x, e1.y + d1.y, e1.z + d1.z, e1.w + d1.w};
    __align__(16) __half h8[8];
#pragma unroll
    for (int i = 0; i < 8; i++)
        h8[i] = __float2half(tanhf(x[i]));
    size_t o = ((size_t)bt * UU + u) * HH + h;
    *(uint4*)(g_A_h + o) = *(const uint4*)h8;
}

// ---------------------------------------------------------------------------
// joint GEMM (HMMA, single fp16 term): out[128u,128v] = A[128,512]@W^T + bias
// 8 warps, 64x32 per warp. K chunks of 64, cp.async double-buffered,
// XOR-swizzled smem rows (128B). 2 CTAs/SM.
// ---------------------------------------------------------------------------
#define KC 64
#define STAGE 32768      // A 16K + W 16K
#define OFF_W 16384

__global__ __launch_bounds__(256, 2) void joint_hmma_kernel(
    const float* __restrict__ b_out, float* __restrict__ out)
{
    extern __shared__ char smem[];
    uint32_t sb = smem_u32(smem);
    int tid = threadIdx.x;
    int lane = tid & 31;
    int wid = tid >> 5;
    int bt = blockIdx.y;
    int v0 = blockIdx.x * 128;

    int wm = (wid & 1) * 64;     // warp m offset (u)
    int wn = (wid >> 1) * 32;    // warp n offset (v)

    const __half* Ag = g_A_h + (size_t)bt * UU * HH;
    const __half* Wg = g_W_h + (size_t)v0 * HH;

    float acc[4][4][4];
#pragma unroll
    for (int i = 0; i < 4; i++)
#pragma unroll
        for (int j = 0; j < 4; j++)
#pragma unroll
            for (int k = 0; k < 4; k++) acc[i][j][k] = 0.0f;

    // ---- fill: copy chunk k0 into buffer bsel (A 128x64 + W 128x64 fp16) --
    auto fill = [&](int bsel, int k0) {
        uint32_t base = sb + bsel * STAGE;
#pragma unroll
        for (int l = 0; l < 4; l++) {
            int idx = tid + l * 256;      // 0..1023
            int r = idx >> 3;             // row 0..127
            int c = idx & 7;              // 16B chunk 0..7
            uint32_t doff = (uint32_t)(r * 128 + ((c ^ (r & 7)) << 4));
            cp_async16(base + doff,        Ag + (size_t)r * HH + k0 + c * 8);
            cp_async16(base + OFF_W + doff, Wg + (size_t)r * HH + k0 + c * 8);
        }
    };

    fill(0, 0);
    cp_commit();

#pragma unroll 1
    for (int c = 0; c < HH / KC; c++) {
        if (c < HH / KC - 1) {
            fill((c + 1) & 1, (c + 1) * KC);
            cp_commit();
            cp_wait1();
        } else {
            cp_wait0();
        }
        __syncthreads();

        uint32_t sA = sb + (c & 1) * STAGE;
        uint32_t sW = sA + OFF_W;

#pragma unroll
        for (int s = 0; s < 4; s++) {
            uint32_t b0[4], b1[4];
#pragma unroll
            for (int ni = 0; ni < 4; ni++) {
                int row = wn + ni * 8 + (lane & 7);
                int chunk = 2 * s + ((lane >> 3) & 1);
                uint32_t addr = sW + row * 128 + ((chunk ^ (row & 7)) << 4);
                ldsm_x2(b0[ni], b1[ni], addr);
            }
#pragma unroll
            for (int mi = 0; mi < 4; mi++) {
                int row = wm + mi * 16 + ((lane >> 3) & 1) * 8 + (lane & 7);
                int chunk = 2 * s + (lane >> 4);
                uint32_t a0, a1, a2, a3;
                ldsm_x4(a0, a1, a2, a3,
                        sA + row * 128 + ((chunk ^ (row & 7)) << 4));
#pragma unroll
                for (int ni = 0; ni < 4; ni++)
                    mma16816(acc[mi][ni], a0, a1, a2, a3, b0[ni], b1[ni]);
            }
        }
        __syncthreads();
    }

    // ---- epilogue: bias + float2 stores straight from registers ----
    int gid = lane >> 2;
    int tig = lane & 3;
    float2 bias2[4];
#pragma unroll
    for (int ni = 0; ni < 4; ni++)
        bias2[ni] = *(const float2*)(b_out + v0 + wn + ni * 8 + tig * 2);

    float* obase = out + (size_t)bt * UU * VV + v0;
#pragma unroll
    for (int mi = 0; mi < 4; mi++) {
        int u0 = wm + mi * 16 + gid;
#pragma unroll
        for (int ni = 0; ni < 4; ni++) {
            int v = wn + ni * 8 + tig * 2;
            float2 r0 = make_float2(acc[mi][ni][0] + bias2[ni].x,
                                    acc[mi][ni][1] + bias2[ni].y);
            float2 r1 = make_float2(acc[mi][ni][2] + bias2[ni].x,
                                    acc[mi][ni][3] + bias2[ni].y);
            *(float2*)(obase + (size_t)u0 * VV + v) = r0;
            *(float2*)(obase + (size_t)(u0 + 8) * VV + v) = r1;
        }
    }
}

// ---------------------------------------------------------------------------
extern "C" void kernel_launch(void* const* d_in, const int* in_sizes, int n_in,
                              void* d_out, int out_size)
{
    const float* enc_out = (const float*)d_in[0];
    const float* dec_out = (const float*)d_in[1];
    const float* W_enc   = (const float*)d_in[2];
    const float* b_enc   = (const float*)d_in[3];
    const float* W_dec   = (const float*)d_in[4];
    const float* W_out   = (const float*)d_in[5];
    const float* b_out   = (const float*)d_in[6];
    float* out = (float*)d_out;

    cudaFuncSetAttribute(joint_hmma_kernel,
                         cudaFuncAttributeMaxDynamicSharedMemorySize, 2 * STAGE);

    float* enc_proj_ptr = nullptr;
    float* dec_proj_ptr = nullptr;
    cudaGetSymbolAddress((void**)&enc_proj_ptr, g_enc_proj);
    cudaGetSymbolAddress((void**)&dec_proj_ptr, g_dec_proj);

    {
        dim3 grid(HH / 64, (BB * TT) / 64);
        proj_kernel<<<grid, 256>>>(enc_out, W_enc, b_enc, enc_proj_ptr, BB * TT, HH, EE);
    }
    {
        dim3 grid(HH / 64, (BB * UU) / 64);
        proj_kernel<<<grid, 256>>>(dec_out, W_dec, nullptr, dec_proj_ptr, BB * UU, HH, DD);
    }
    prep_w_kernel<<<(VV * HH + 255) / 256, 256>>>(W_out);
    {
        dim3 grid(BT, UU / 4);
        act_kernel<<<grid, 256>>>();
    }
    {
        dim3 grid(VV / 128, BT);   // (5, 1024)
        joint_hmma_kernel<<<grid, 256, 2 * STAGE>>>(b_out, out);
    }
}

// round 6
// speedup vs baseline: 6.1384x; 1.0696x over previous
#include <cuda_runtime.h>
#include <cuda_fp16.h>
#include <math.h>
#include <stdint.h>

// ---------------- problem constants ----------------
#define BB 4
#define TT 256
#define UU 128
#define EE 512
#define DD 640
#define HH 512
#define VV 640
#define BT (BB*TT)          // 1024

// ---------------- device scratch ----------------
__device__ float g_enc_proj[BT * HH];        // [1024, 512]
__device__ float g_dec_proj[BB * UU * HH];   // [512, 512]
__device__ __half g_A_h[BT * UU * HH];       // fp16 tanh activations (134 MB)
__device__ __half g_W_h[VV * HH];            // W_out transposed [v][h], fp16

// ---------------- PTX helpers (baseline ISA only) ----------------
__device__ __forceinline__ uint32_t smem_u32(const void* p) {
    uint32_t a;
    asm("{ .reg .u64 t; cvta.to.shared.u64 t, %1; cvt.u32.u64 %0, t; }"
        : "=r"(a) : "l"(p));
    return a;
}
__device__ __forceinline__ float tanh_fast(float x) {
    float y;
    asm("tanh.approx.f32 %0, %1;" : "=f"(y) : "f"(x));
    return y;
}
__device__ __forceinline__ void cp_async16(uint32_t dst, const void* src) {
    asm volatile("cp.async.cg.shared.global [%0], [%1], 16;"
                 :: "r"(dst), "l"(src) : "memory");
}
__device__ __forceinline__ void cp_commit() {
    asm volatile("cp.async.commit_group;" ::: "memory");
}
__device__ __forceinline__ void cp_wait1() {
    asm volatile("cp.async.wait_group 1;" ::: "memory");
}
__device__ __forceinline__ void cp_wait0() {
    asm volatile("cp.async.wait_group 0;" ::: "memory");
}
__device__ __forceinline__ void ldsm_x4(uint32_t& r0, uint32_t& r1,
                                        uint32_t& r2, uint32_t& r3, uint32_t addr) {
    asm volatile("ldmatrix.sync.aligned.m8n8.x4.shared.b16 {%0,%1,%2,%3}, [%4];"
                 : "=r"(r0), "=r"(r1), "=r"(r2), "=r"(r3) : "r"(addr));
}
__device__ __forceinline__ void mma16816(float* c, uint32_t a0, uint32_t a1,
                                         uint32_t a2, uint32_t a3,
                                         uint32_t b0, uint32_t b1) {
    asm volatile(
        "mma.sync.aligned.m16n8k16.row.col.f32.f16.f16.f32 "
        "{%0,%1,%2,%3}, {%4,%5,%6,%7}, {%8,%9}, {%0,%1,%2,%3};"
        : "+f"(c[0]), "+f"(c[1]), "+f"(c[2]), "+f"(c[3])
        : "r"(a0), "r"(a1), "r"(a2), "r"(a3), "r"(b0), "r"(b1));
}

// ---------------------------------------------------------------------------
// proj: C[M,N] = A[M,K] @ W[K,N] (+ bias). fp32, 32x64 tile, 128 threads.
// ---------------------------------------------------------------------------
__global__ __launch_bounds__(128) void proj_kernel(
    const float* __restrict__ A, const float* __restrict__ W,
    const float* __restrict__ bias, float* __restrict__ C,
    int M, int N, int K)
{
    __shared__ float Ast[32][33];   // [k][m]
    __shared__ float Ws[32][68];    // [k][n]
    int tid = threadIdx.x;
    int tx = tid & 15, ty = tid >> 4;
    int m0 = blockIdx.y * 32, n0 = blockIdx.x * 64;

    float acc[4][4];
#pragma unroll
    for (int i = 0; i < 4; i++)
#pragma unroll
        for (int j = 0; j < 4; j++) acc[i][j] = 0.0f;

    for (int k0 = 0; k0 < K; k0 += 32) {
#pragma unroll
        for (int l = 0; l < 8; l++) {
            int idx = tid + l * 128;
            Ast[idx & 31][idx >> 5] = A[(m0 + (idx >> 5)) * K + k0 + (idx & 31)];
        }
#pragma unroll
        for (int l = 0; l < 16; l++) {
            int idx = tid + l * 128;
            Ws[idx >> 6][idx & 63] = W[(k0 + (idx >> 6)) * N + n0 + (idx & 63)];
        }
        __syncthreads();
#pragma unroll
        for (int k = 0; k < 32; k++) {
            float a[4], b[4];
#pragma unroll
            for (int i = 0; i < 4; i++) a[i] = Ast[k][ty * 4 + i];
#pragma unroll
            for (int j = 0; j < 4; j++) b[j] = Ws[k][tx * 4 + j];
#pragma unroll
            for (int i = 0; i < 4; i++)
#pragma unroll
                for (int j = 0; j < 4; j++)
                    acc[i][j] = fmaf(a[i], b[j], acc[i][j]);
        }
        __syncthreads();
    }
#pragma unroll
    for (int i = 0; i < 4; i++)
#pragma unroll
        for (int j = 0; j < 4; j++) {
            float v = acc[i][j];
            if (bias) v += bias[n0 + tx * 4 + j];
            C[(m0 + ty * 4 + i) * N + n0 + tx * 4 + j] = v;
        }
}

// ---------------------------------------------------------------------------
// prep_w: transpose + fp16 cast of W_out [H,V] -> [V,H]
// ---------------------------------------------------------------------------
__global__ __launch_bounds__(256) void prep_w_kernel(const float* __restrict__ W_out)
{
    int idx = blockIdx.x * 256 + threadIdx.x;
    if (idx >= VV * HH) return;
    int v = idx / HH, h = idx - v * HH;
    g_W_h[idx] = __float2half(W_out[h * VV + v]);
}

// ---------------------------------------------------------------------------
// act: A[bt][u][h] = tanh(enc_proj[bt][h] + dec_proj[b][u][h]) -> fp16 (HW tanh)
// ---------------------------------------------------------------------------
__global__ __launch_bounds__(256) void act_kernel()
{
    int bt = blockIdx.x;
    int b = bt >> 8;
    int u = blockIdx.y * 4 + (threadIdx.x >> 6);
    int h = (threadIdx.x & 63) * 8;
    const float* ep = g_enc_proj + bt * HH + h;
    const float* dp = g_dec_proj + (b * UU + u) * HH + h;
    float4 e0 = *(const float4*)ep, e1 = *(const float4*)(ep + 4);
    float4 d0 = *(const float4*)dp, d1 = *(const float4*)(dp + 4);
    float x[8] = {e0.x + d0.x, e0.y + d0.y, e0.z + d0.z, e0.w + d0.w,
                  e1.x + d1.x, e1.y + d1.y, e1.z + d1.z, e1.w + d1.w};
    __align__(16) __half h8[8];
#pragma unroll
    for (int i = 0; i < 8; i++)
        h8[i] = __float2half(tanh_fast(x[i]));
    size_t o = ((size_t)bt * UU + u) * HH + h;
    *(uint4*)(g_A_h + o) = *(const uint4*)h8;
}

// ---------------------------------------------------------------------------
// joint GEMM (HMMA fp16): out[128u,128v] = A[128,512]@W^T + bias
// 4 warps, 64x64 per warp (2x2). K chunks of 64, cp.async double-buffered,
// XOR-swizzled 128B smem rows. 2 CTAs/SM.
// ---------------------------------------------------------------------------
#define KC 64
#define STAGE 32768      // A 16K + W 16K
#define OFF_W 16384

__global__ __launch_bounds__(128, 2) void joint_hmma_kernel(
    const float* __restrict__ b_out, float* __restrict__ out)
{
    extern __shared__ char smem[];
    uint32_t sb = smem_u32(smem);
    int tid = threadIdx.x;
    int lane = tid & 31;
    int wid = tid >> 5;
    int bt = blockIdx.y;
    int v0 = blockIdx.x * 128;

    int wm = (wid & 1) * 64;     // warp m offset (u)
    int wn = (wid >> 1) * 64;    // warp n offset (v)

    const __half* Ag = g_A_h + (size_t)bt * UU * HH;
    const __half* Wg = g_W_h + (size_t)v0 * HH;

    float acc[4][8][4];
#pragma unroll
    for (int i = 0; i < 4; i++)
#pragma unroll
        for (int j = 0; j < 8; j++)
#pragma unroll
            for (int k = 0; k < 4; k++) acc[i][j][k] = 0.0f;

    // ---- fill: stage chunk k0 into buffer bsel (A 128x64 + W 128x64 fp16) --
    auto fill = [&](int bsel, int k0) {
        uint32_t base = sb + bsel * STAGE;
#pragma unroll
        for (int l = 0; l < 8; l++) {
            int idx = tid + l * 128;      // 0..1023
            int r = idx >> 3;             // row 0..127
            int c = idx & 7;              // 16B chunk 0..7
            uint32_t doff = (uint32_t)(r * 128 + ((c ^ (r & 7)) << 4));
            cp_async16(base + doff,         Ag + (size_t)r * HH + k0 + c * 8);
            cp_async16(base + OFF_W + doff, Wg + (size_t)r * HH + k0 + c * 8);
        }
    };

    fill(0, 0);
    cp_commit();

#pragma unroll 1
    for (int c = 0; c < HH / KC; c++) {
        if (c < HH / KC - 1) {
            fill((c + 1) & 1, (c + 1) * KC);
            cp_commit();
            cp_wait1();
        } else {
            cp_wait0();
        }
        __syncthreads();

        uint32_t sA = sb + (c & 1) * STAGE;
        uint32_t sW = sA + OFF_W;

#pragma unroll
        for (int s = 0; s < 4; s++) {
            // B fragments: 8 n8 frags via 4 ldsm_x4 (each covers 2 n8 blocks)
            uint32_t b0[8], b1[8];
#pragma unroll
            for (int jj = 0; jj < 4; jj++) {
                int row = wn + jj * 16 + ((lane >> 4) & 1) * 8 + (lane & 7);
                int chunk = 2 * s + ((lane >> 3) & 1);
                ldsm_x4(b0[jj * 2], b1[jj * 2], b0[jj * 2 + 1], b1[jj * 2 + 1],
                        sW + row * 128 + ((chunk ^ (row & 7)) << 4));
            }
            // A fragments + MMAs
#pragma unroll
            for (int mi = 0; mi < 4; mi++) {
                int row = wm + mi * 16 + ((lane >> 3) & 1) * 8 + (lane & 7);
                int chunk = 2 * s + (lane >> 4);
                uint32_t a0, a1, a2, a3;
                ldsm_x4(a0, a1, a2, a3,
                        sA + row * 128 + ((chunk ^ (row & 7)) << 4));
#pragma unroll
                for (int ni = 0; ni < 8; ni++)
                    mma16816(acc[mi][ni], a0, a1, a2, a3, b0[ni], b1[ni]);
            }
        }
        __syncthreads();
    }

    // ---- epilogue: bias + float2 stores straight from registers ----
    int gid = lane >> 2;
    int tig = lane & 3;
    float2 bias2[8];
#pragma unroll
    for (int ni = 0; ni < 8; ni++)
        bias2[ni] = *(const float2*)(b_out + v0 + wn + ni * 8 + tig * 2);

    float* obase = out + (size_t)bt * UU * VV + v0;
#pragma unroll
    for (int mi = 0; mi < 4; mi++) {
        int u0 = wm + mi * 16 + gid;
#pragma unroll
        for (int ni = 0; ni < 8; ni++) {
            int v = wn + ni * 8 + tig * 2;
            float2 r0 = make_float2(acc[mi][ni][0] + bias2[ni].x,
                                    acc[mi][ni][1] + bias2[ni].y);
            float2 r1 = make_float2(acc[mi][ni][2] + bias2[ni].x,
                                    acc[mi][ni][3] + bias2[ni].y);
            *(float2*)(obase + (size_t)u0 * VV + v) = r0;
            *(float2*)(obase + (size_t)(u0 + 8) * VV + v) = r1;
        }
    }
}

// ---------------------------------------------------------------------------
extern "C" void kernel_launch(void* const* d_in, const int* in_sizes, int n_in,
                              void* d_out, int out_size)
{
    const float* enc_out = (const float*)d_in[0];
    const float* dec_out = (const float*)d_in[1];
    const float* W_enc   = (const float*)d_in[2];
    const float* b_enc   = (const float*)d_in[3];
    const float* W_dec   = (const float*)d_in[4];
    const float* W_out   = (const float*)d_in[5];
    const float* b_out   = (const float*)d_in[6];
    float* out = (float*)d_out;

    cudaFuncSetAttribute(joint_hmma_kernel,
                         cudaFuncAttributeMaxDynamicSharedMemorySize, 2 * STAGE);

    float* enc_proj_ptr = nullptr;
    float* dec_proj_ptr = nullptr;
    cudaGetSymbolAddress((void**)&enc_proj_ptr, g_enc_proj);
    cudaGetSymbolAddress((void**)&dec_proj_ptr, g_dec_proj);

    {
        dim3 grid(HH / 64, (BB * TT) / 32);   // (8, 32) = 256 CTAs
        proj_kernel<<<grid, 128>>>(enc_out, W_enc, b_enc, enc_proj_ptr, BB * TT, HH, EE);
    }
    {
        dim3 grid(HH / 64, (BB * UU) / 32);   // (8, 16) = 128 CTAs
        proj_kernel<<<grid, 128>>>(dec_out, W_dec, nullptr, dec_proj_ptr, BB * UU, HH, DD);
    }
    prep_w_kernel<<<(VV * HH + 255) / 256, 256>>>(W_out);
    {
        dim3 grid(BT, UU / 4);
        act_kernel<<<grid, 256>>>();
    }
    {
        dim3 grid(VV / 128, BT);   // (5, 1024)
        joint_hmma_kernel<<<grid, 128, 2 * STAGE>>>(b_out, out);
    }
}